// round 1
// baseline (speedup 1.0000x reference)
#include <cuda_runtime.h>

#define VOCAB  50000
#define EMBED  256
#define MAXLEN 512
#define UNITS  32
#define F1     16
#define BATCH  512

// Scratch: P = emb_table @ Wx  [VOCAB, UNITS]  (6.4 MB, fits L2)
__device__ float g_P[VOCAB * UNITS];

// ---------------------------------------------------------------------------
// Kernel 1: P[v][j] = sum_e emb[v][e] * Wx[e][j]
// Block = 256 threads, covers 64 vocab rows x 32 cols.
// Thread (j = tid&31, rg = tid>>5) computes 8 rows for its column j.
// Within a warp rg is constant -> emb_s reads are uniform (broadcast, N=1);
// wx_s reads are lane-indexed -> conflict-free. FFMA-pipe bound by design.
// ---------------------------------------------------------------------------
#define PK_ROWS    64
#define PK_THREADS 256
#define PK_SMEM    ((EMBED*UNITS + PK_ROWS*EMBED) * 4)   // 32KB + 64KB = 96KB

__global__ void __launch_bounds__(PK_THREADS)
compute_P_kernel(const float* __restrict__ emb, const float* __restrict__ Wx)
{
    extern __shared__ float smem[];
    float* wx_s  = smem;                  // [EMBED][UNITS]
    float* emb_s = smem + EMBED * UNITS;  // [PK_ROWS][EMBED]

    const int tid = threadIdx.x;
    const int v0  = blockIdx.x * PK_ROWS;

    // stage Wx (32KB)
    #pragma unroll
    for (int i = tid; i < EMBED * UNITS; i += PK_THREADS)
        wx_s[i] = Wx[i];

    // stage emb tile (64KB) via float4, zero-fill OOB rows
    {
        const float4* e4  = reinterpret_cast<const float4*>(emb);
        float4*       es4 = reinterpret_cast<float4*>(emb_s);
        const int base4 = v0 * (EMBED / 4);
        const int max4  = VOCAB * (EMBED / 4);
        #pragma unroll
        for (int i = tid; i < PK_ROWS * (EMBED / 4); i += PK_THREADS) {
            int gi = base4 + i;
            es4[i] = (gi < max4) ? e4[gi] : make_float4(0.f, 0.f, 0.f, 0.f);
        }
    }
    __syncthreads();

    const int j  = tid & 31;
    const int rg = tid >> 5;                    // 0..7 -> rows rg*8 .. rg*8+7
    const float* er = emb_s + rg * 8 * EMBED;

    float acc[8];
    #pragma unroll
    for (int r = 0; r < 8; r++) acc[r] = 0.f;

    #pragma unroll 4
    for (int e = 0; e < EMBED; e += 4) {
        const float w0 = wx_s[(e + 0) * UNITS + j];
        const float w1 = wx_s[(e + 1) * UNITS + j];
        const float w2 = wx_s[(e + 2) * UNITS + j];
        const float w3 = wx_s[(e + 3) * UNITS + j];
        #pragma unroll
        for (int r = 0; r < 8; r++) {
            float4 ev = *reinterpret_cast<const float4*>(er + r * EMBED + e);
            acc[r] = fmaf(ev.x, w0, acc[r]);
            acc[r] = fmaf(ev.y, w1, acc[r]);
            acc[r] = fmaf(ev.z, w2, acc[r]);
            acc[r] = fmaf(ev.w, w3, acc[r]);
        }
    }

    #pragma unroll
    for (int r = 0; r < 8; r++) {
        int v = v0 + rg * 8 + r;
        if (v < VOCAB) g_P[v * UNITS + j] = acc[r];
    }
}

// ---------------------------------------------------------------------------
// Kernel 2: RNN recurrence + head. One warp per batch row.
// h distributed one unit per lane; Wh column register-resident per lane.
// Per step: prefetched P-row gather, 32 shfl broadcasts + 32 FMAs (4 chains),
// tanh via __expf (accurate to ~1e-6). Head fused at the end.
// Launch: 64 blocks x 256 threads -> 8 warps/SM on 64 SMs = 2 warps/SMSP,
// so one warp's tanh/shfl latency hides under the other's issue stream.
// ---------------------------------------------------------------------------
#define R_WARPS   8
#define R_THREADS 256

__global__ void __launch_bounds__(R_THREADS)
rnn_kernel(const int*   __restrict__ tokens,
           const float* __restrict__ Wh,
           const float* __restrict__ bias,
           const float* __restrict__ W1,
           const float* __restrict__ b1,
           const float* __restrict__ W2,
           const float* __restrict__ b2,
           float*       __restrict__ out)
{
    const unsigned FULL = 0xffffffffu;
    const int lane = threadIdx.x & 31;
    const int wid  = threadIdx.x >> 5;
    const int b    = blockIdx.x * R_WARPS + wid;     // 0..511

    // register-resident Wh column for this lane: wh[k] = Wh[k][lane]
    float wh[UNITS];
    #pragma unroll
    for (int k = 0; k < UNITS; k++) wh[k] = Wh[k * UNITS + lane];
    const float bv = bias[lane];

    const int* trow = tokens + b * MAXLEN;

    float h = 0.f;

    // token chunk prefetch (32 tokens per LDG, distributed across lanes)
    int chunk = trow[lane];
    int tok0  = __shfl_sync(FULL, chunk, 0);
    float pv  = g_P[tok0 * UNITS + lane];            // P row for step 0

    for (int c = 0; c < MAXLEN / 32; c++) {
        int nchunk = (c + 1 < MAXLEN / 32) ? trow[(c + 1) * 32 + lane] : 0;
        #pragma unroll
        for (int s = 0; s < 32; s++) {
            // prefetch next step's P row (depth-1; L2-resident)
            int ntok = (s < 31) ? __shfl_sync(FULL, chunk, s + 1)
                                : __shfl_sync(FULL, nchunk, 0);
            float pnext = g_P[ntok * UNITS + lane];

            float a0 = pv + bv, a1 = 0.f, a2 = 0.f, a3 = 0.f;
            #pragma unroll
            for (int k = 0; k < UNITS; k += 4) {
                float h0 = __shfl_sync(FULL, h, k + 0);
                float h1 = __shfl_sync(FULL, h, k + 1);
                float h2 = __shfl_sync(FULL, h, k + 2);
                float h3 = __shfl_sync(FULL, h, k + 3);
                a0 = fmaf(h0, wh[k + 0], a0);
                a1 = fmaf(h1, wh[k + 1], a1);
                a2 = fmaf(h2, wh[k + 2], a2);
                a3 = fmaf(h3, wh[k + 3], a3);
            }
            float z = (a0 + a1) + (a2 + a3);
            // tanh(z) = 1 - 2/(exp(2z)+1); exact at +-inf, ~1e-6 rel err
            float e = __expf(2.f * z);
            h = 1.f - __fdividef(2.f, e + 1.f);
            pv = pnext;
        }
        chunk = nchunk;
    }

    // ---- head: z = (h @ W1 + b1) @ W2 + b2 ; out = sigmoid(z) ----
    float w1c[UNITS];
    #pragma unroll
    for (int k = 0; k < UNITS; k++)
        w1c[k] = (lane < F1) ? W1[k * F1 + lane] : 0.f;

    float y = (lane < F1) ? b1[lane] : 0.f;
    #pragma unroll
    for (int k = 0; k < UNITS; k++)
        y = fmaf(__shfl_sync(FULL, h, k), w1c[k], y);

    float w2v = (lane < F1) ? W2[lane] : 0.f;
    float contrib = y * w2v;                          // zero on lanes >= F1
    #pragma unroll
    for (int off = 16; off > 0; off >>= 1)
        contrib += __shfl_xor_sync(FULL, contrib, off);

    if (lane == 0) {
        float zz = contrib + b2[0];
        out[b] = __fdividef(1.f, 1.f + __expf(-zz));
    }
}

// ---------------------------------------------------------------------------
extern "C" void kernel_launch(void* const* d_in, const int* in_sizes, int n_in,
                              void* d_out, int out_size)
{
    const int*   tokens = (const int*)  d_in[0];
    const float* emb    = (const float*)d_in[1];
    const float* Wx     = (const float*)d_in[2];
    const float* Wh     = (const float*)d_in[3];
    const float* bias   = (const float*)d_in[4];
    const float* W1     = (const float*)d_in[5];
    const float* b1     = (const float*)d_in[6];
    const float* W2     = (const float*)d_in[7];
    const float* b2     = (const float*)d_in[8];
    float* out = (float*)d_out;

    // 96KB dynamic smem for kernel 1 (idempotent; not a stream op)
    cudaFuncSetAttribute((const void*)compute_P_kernel,
                         cudaFuncAttributeMaxDynamicSharedMemorySize, PK_SMEM);

    compute_P_kernel<<<(VOCAB + PK_ROWS - 1) / PK_ROWS, PK_THREADS, PK_SMEM>>>(emb, Wx);
    rnn_kernel<<<BATCH / R_WARPS, R_THREADS>>>(tokens, Wh, bias, W1, b1, W2, b2, out);
}

// round 2
// speedup vs baseline: 1.1387x; 1.1387x over previous
#include <cuda_runtime.h>

#define VOCAB  50000
#define EMBED  256
#define MAXLEN 512
#define UNITS  32
#define F1     16
#define BATCH  512

// Scratch: P = emb_table @ Wx + b  [VOCAB, UNITS]  (6.4 MB, L2-resident)
__device__ float g_P[VOCAB * UNITS];

// ---------------------------------------------------------------------------
// Kernel 1: P[v][j] = sum_e emb[v][e] * Wx[e][j] + b[j]
// Unchanged from round 1 (measured at FFMA roofline ~22us) except bias fold.
// ---------------------------------------------------------------------------
#define PK_ROWS    64
#define PK_THREADS 256
#define PK_SMEM    ((EMBED*UNITS + PK_ROWS*EMBED) * 4)   // 32KB + 64KB = 96KB

__global__ void __launch_bounds__(PK_THREADS)
compute_P_kernel(const float* __restrict__ emb, const float* __restrict__ Wx,
                 const float* __restrict__ bias)
{
    extern __shared__ float smem[];
    float* wx_s  = smem;                  // [EMBED][UNITS]
    float* emb_s = smem + EMBED * UNITS;  // [PK_ROWS][EMBED]

    const int tid = threadIdx.x;
    const int v0  = blockIdx.x * PK_ROWS;

    #pragma unroll
    for (int i = tid; i < EMBED * UNITS; i += PK_THREADS)
        wx_s[i] = Wx[i];

    {
        const float4* e4  = reinterpret_cast<const float4*>(emb);
        float4*       es4 = reinterpret_cast<float4*>(emb_s);
        const int base4 = v0 * (EMBED / 4);
        const int max4  = VOCAB * (EMBED / 4);
        #pragma unroll
        for (int i = tid; i < PK_ROWS * (EMBED / 4); i += PK_THREADS) {
            int gi = base4 + i;
            es4[i] = (gi < max4) ? e4[gi] : make_float4(0.f, 0.f, 0.f, 0.f);
        }
    }
    __syncthreads();

    const int j  = tid & 31;
    const int rg = tid >> 5;
    const float* er = emb_s + rg * 8 * EMBED;
    const float bv = bias[j];

    float acc[8];
    #pragma unroll
    for (int r = 0; r < 8; r++) acc[r] = bv;

    #pragma unroll 4
    for (int e = 0; e < EMBED; e += 4) {
        const float w0 = wx_s[(e + 0) * UNITS + j];
        const float w1 = wx_s[(e + 1) * UNITS + j];
        const float w2 = wx_s[(e + 2) * UNITS + j];
        const float w3 = wx_s[(e + 3) * UNITS + j];
        #pragma unroll
        for (int r = 0; r < 8; r++) {
            float4 ev = *reinterpret_cast<const float4*>(er + r * EMBED + e);
            acc[r] = fmaf(ev.x, w0, acc[r]);
            acc[r] = fmaf(ev.y, w1, acc[r]);
            acc[r] = fmaf(ev.z, w2, acc[r]);
            acc[r] = fmaf(ev.w, w3, acc[r]);
        }
    }

    #pragma unroll
    for (int r = 0; r < 8; r++) {
        int v = v0 + rg * 8 + r;
        if (v < VOCAB) g_P[v * UNITS + j] = acc[r];
    }
}

// ---------------------------------------------------------------------------
// Kernel 2: RNN recurrence + head. One warp per batch row, lane = unit.
// h-broadcast via SMEM (1 STS + syncwarp + 8 LDS.128 broadcasts) instead of
// 32 SHFLs -> MIO pipe pressure drops ~3.5x. Tokens staged in SMEM (uniform
// LDS broadcast per step). P-row gather prefetched depth-2 (step ~150cyc <
// L2 hit 234cyc). Layout: 128 blocks x 4 warps = 1 warp/SMSP on 128 SMs
// (latency-bound regime; no pipe sharing).
// ---------------------------------------------------------------------------
#define R_WARPS   4
#define R_THREADS 128

__global__ void __launch_bounds__(R_THREADS)
rnn_kernel(const int*   __restrict__ tokens,
           const float* __restrict__ W1,
           const float* __restrict__ b1,
           const float* __restrict__ W2,
           const float* __restrict__ b2,
           const float* __restrict__ Wh,
           float*       __restrict__ out)
{
    __shared__ __align__(16) float h_s[R_WARPS][UNITS];
    __shared__ int tok_s[R_WARPS][MAXLEN];

    const unsigned FULL = 0xffffffffu;
    const int tid  = threadIdx.x;
    const int lane = tid & 31;
    const int wid  = tid >> 5;
    const int b    = blockIdx.x * R_WARPS + wid;     // 0..511

    // stage this block's 4 token rows (contiguous 2048 ints) via int4
    {
        const int4* src = reinterpret_cast<const int4*>(tokens + blockIdx.x * R_WARPS * MAXLEN);
        int4* dst = reinterpret_cast<int4*>(&tok_s[0][0]);
        #pragma unroll
        for (int i = tid; i < R_WARPS * MAXLEN / 4; i += R_THREADS)
            dst[i] = src[i];
    }
    __syncthreads();

    // register-resident Wh column: wh[k] = Wh[k][lane]
    float wh[UNITS];
    #pragma unroll
    for (int k = 0; k < UNITS; k++) wh[k] = Wh[k * UNITS + lane];

    const int* trow = tok_s[wid];
    const float4* hrow4 = reinterpret_cast<const float4*>(h_s[wid]);

    float h = 0.f;

    // depth-2 P-row prefetch (bias already folded into P)
    float pv  = g_P[trow[0] * UNITS + lane];
    float pv1 = g_P[trow[1] * UNITS + lane];

    #pragma unroll 8
    for (int t = 0; t < MAXLEN; t++) {
        // exchange h_{t-1} across the warp via smem
        h_s[wid][lane] = h;
        __syncwarp();
        float4 x0 = hrow4[0];
        float4 x1 = hrow4[1];
        float4 x2 = hrow4[2];
        float4 x3 = hrow4[3];
        float4 x4 = hrow4[4];
        float4 x5 = hrow4[5];
        float4 x6 = hrow4[6];
        float4 x7 = hrow4[7];
        __syncwarp();   // protect smem from next iteration's STS

        // prefetch P row for step t+2 (independent of the FMA chain)
        int t2 = (t + 2 < MAXLEN) ? (t + 2) : (MAXLEN - 1);
        float pv2 = g_P[trow[t2] * UNITS + lane];

        // z = pv + sum_k h[k] * wh[k]   (4 accumulator chains, depth 8)
        float a0 = pv, a1 = 0.f, a2 = 0.f, a3 = 0.f;
        a0 = fmaf(x0.x, wh[0],  a0); a1 = fmaf(x0.y, wh[1],  a1);
        a2 = fmaf(x0.z, wh[2],  a2); a3 = fmaf(x0.w, wh[3],  a3);
        a0 = fmaf(x1.x, wh[4],  a0); a1 = fmaf(x1.y, wh[5],  a1);
        a2 = fmaf(x1.z, wh[6],  a2); a3 = fmaf(x1.w, wh[7],  a3);
        a0 = fmaf(x2.x, wh[8],  a0); a1 = fmaf(x2.y, wh[9],  a1);
        a2 = fmaf(x2.z, wh[10], a2); a3 = fmaf(x2.w, wh[11], a3);
        a0 = fmaf(x3.x, wh[12], a0); a1 = fmaf(x3.y, wh[13], a1);
        a2 = fmaf(x3.z, wh[14], a2); a3 = fmaf(x3.w, wh[15], a3);
        a0 = fmaf(x4.x, wh[16], a0); a1 = fmaf(x4.y, wh[17], a1);
        a2 = fmaf(x4.z, wh[18], a2); a3 = fmaf(x4.w, wh[19], a3);
        a0 = fmaf(x5.x, wh[20], a0); a1 = fmaf(x5.y, wh[21], a1);
        a2 = fmaf(x5.z, wh[22], a2); a3 = fmaf(x5.w, wh[23], a3);
        a0 = fmaf(x6.x, wh[24], a0); a1 = fmaf(x6.y, wh[25], a1);
        a2 = fmaf(x6.z, wh[26], a2); a3 = fmaf(x6.w, wh[27], a3);
        a0 = fmaf(x7.x, wh[28], a0); a1 = fmaf(x7.y, wh[29], a1);
        a2 = fmaf(x7.z, wh[30], a2); a3 = fmaf(x7.w, wh[31], a3);

        float z = (a0 + a1) + (a2 + a3);
        // tanh(z) = 1 - 2/(exp(2z)+1); exact at +-inf, ~1e-6 rel err
        float e = __expf(2.f * z);
        h = 1.f - __fdividef(2.f, e + 1.f);

        pv = pv1; pv1 = pv2;
    }

    // ---- head: z = (h @ W1 + b1) @ W2 + b2 ; out = sigmoid(z) ----
    // (once per row; shfl cost negligible here)
    float w1c[UNITS];
    #pragma unroll
    for (int k = 0; k < UNITS; k++)
        w1c[k] = (lane < F1) ? W1[k * F1 + lane] : 0.f;

    float y = (lane < F1) ? b1[lane] : 0.f;
    #pragma unroll
    for (int k = 0; k < UNITS; k++)
        y = fmaf(__shfl_sync(FULL, h, k), w1c[k], y);

    float w2v = (lane < F1) ? W2[lane] : 0.f;
    float contrib = y * w2v;
    #pragma unroll
    for (int off = 16; off > 0; off >>= 1)
        contrib += __shfl_xor_sync(FULL, contrib, off);

    if (lane == 0) {
        float zz = contrib + b2[0];
        out[b] = __fdividef(1.f, 1.f + __expf(-zz));
    }
}

// ---------------------------------------------------------------------------
extern "C" void kernel_launch(void* const* d_in, const int* in_sizes, int n_in,
                              void* d_out, int out_size)
{
    const int*   tokens = (const int*)  d_in[0];
    const float* emb    = (const float*)d_in[1];
    const float* Wx     = (const float*)d_in[2];
    const float* Wh     = (const float*)d_in[3];
    const float* bias   = (const float*)d_in[4];
    const float* W1     = (const float*)d_in[5];
    const float* b1     = (const float*)d_in[6];
    const float* W2     = (const float*)d_in[7];
    const float* b2     = (const float*)d_in[8];
    float* out = (float*)d_out;

    cudaFuncSetAttribute((const void*)compute_P_kernel,
                         cudaFuncAttributeMaxDynamicSharedMemorySize, PK_SMEM);

    compute_P_kernel<<<(VOCAB + PK_ROWS - 1) / PK_ROWS, PK_THREADS, PK_SMEM>>>(emb, Wx, bias);
    rnn_kernel<<<BATCH / R_WARPS, R_THREADS>>>(tokens, W1, b1, W2, b2, Wh, out);
}

// round 3
// speedup vs baseline: 1.2501x; 1.0979x over previous
#include <cuda_runtime.h>

#define VOCAB  50000
#define EMBED  256
#define MAXLEN 512
#define UNITS  32
#define F1     16
#define BATCH  512

typedef unsigned long long ull;

// C = 2*log2(e): folds tanh's exp(2z)=2^(C*z) scaling into P and Wh.
#define CSCALE 2.8853900817779268f

// Scratch: P = C * (emb_table @ Wx + b)  [VOCAB, UNITS]  (6.4 MB, L2-resident)
__device__ float g_P[VOCAB * UNITS];

// ---- f32x2 packed helpers (sm_103a) --------------------------------------
__device__ __forceinline__ ull pack2(float lo, float hi) {
    ull d; asm("mov.b64 %0, {%1, %2};" : "=l"(d) : "f"(lo), "f"(hi)); return d;
}
__device__ __forceinline__ void unpack2(ull s, float& lo, float& hi) {
    asm("mov.b64 {%0, %1}, %2;" : "=f"(lo), "=f"(hi) : "l"(s));
}
__device__ __forceinline__ ull fma2(ull a, ull b, ull c) {
    ull d; asm("fma.rn.f32x2 %0, %1, %2, %3;" : "=l"(d) : "l"(a), "l"(b), "l"(c)); return d;
}
__device__ __forceinline__ ull add2(ull a, ull b) {
    ull d; asm("add.rn.f32x2 %0, %1, %2;" : "=l"(d) : "l"(a), "l"(b)); return d;
}
__device__ __forceinline__ float ex2f(float x) {
    float y; asm("ex2.approx.f32 %0, %1;" : "=f"(y) : "f"(x)); return y;
}
__device__ __forceinline__ float rcpf(float x) {
    float y; asm("rcp.approx.f32 %0, %1;" : "=f"(y) : "f"(x)); return y;
}

// ---------------------------------------------------------------------------
// Kernel 1: P[v][j] = C * (sum_e emb[v][e]*Wx[e][j] + b[j]), packed f32x2.
// ---------------------------------------------------------------------------
#define PK_ROWS    64
#define PK_THREADS 256
#define PK_SMEM    ((EMBED*UNITS + PK_ROWS*EMBED) * 4)   // 32KB + 64KB = 96KB

__global__ void __launch_bounds__(PK_THREADS, 1)
compute_P_kernel(const float* __restrict__ emb, const float* __restrict__ Wx,
                 const float* __restrict__ bias)
{
    extern __shared__ float smem[];
    float* wx_s  = smem;                  // [EMBED][UNITS]
    float* emb_s = smem + EMBED * UNITS;  // [PK_ROWS][EMBED]

    const int tid = threadIdx.x;
    const int v0  = blockIdx.x * PK_ROWS;

    #pragma unroll
    for (int i = tid; i < EMBED * UNITS; i += PK_THREADS)
        wx_s[i] = Wx[i];

    {
        const float4* e4  = reinterpret_cast<const float4*>(emb);
        float4*       es4 = reinterpret_cast<float4*>(emb_s);
        const int base4 = v0 * (EMBED / 4);
        const int max4  = VOCAB * (EMBED / 4);
        #pragma unroll
        for (int i = tid; i < PK_ROWS * (EMBED / 4); i += PK_THREADS) {
            int gi = base4 + i;
            es4[i] = (gi < max4) ? e4[gi] : make_float4(0.f, 0.f, 0.f, 0.f);
        }
    }
    __syncthreads();

    const int j  = tid & 31;
    const int rg = tid >> 5;
    const float* er = emb_s + rg * 8 * EMBED;
    const float bv = bias[j];

    ull acc[8];
    #pragma unroll
    for (int r = 0; r < 8; r++) acc[r] = pack2(bv, 0.f);

    #pragma unroll 4
    for (int e = 0; e < EMBED; e += 4) {
        const float w0 = wx_s[(e + 0) * UNITS + j];
        const float w1 = wx_s[(e + 1) * UNITS + j];
        const float w2 = wx_s[(e + 2) * UNITS + j];
        const float w3 = wx_s[(e + 3) * UNITS + j];
        const ull w01 = pack2(w0, w1);
        const ull w23 = pack2(w2, w3);
        #pragma unroll
        for (int r = 0; r < 8; r++) {
            ulonglong2 ev = *reinterpret_cast<const ulonglong2*>(er + r * EMBED + e);
            acc[r] = fma2(ev.x, w01, acc[r]);
            acc[r] = fma2(ev.y, w23, acc[r]);
        }
    }

    #pragma unroll
    for (int r = 0; r < 8; r++) {
        int v = v0 + rg * 8 + r;
        if (v < VOCAB) {
            float lo, hi; unpack2(acc[r], lo, hi);
            g_P[v * UNITS + j] = CSCALE * (lo + hi);
        }
    }
}

// ---------------------------------------------------------------------------
// Kernel 2: RNN recurrence + head. One warp per batch row, lane = unit.
// Exchanged quantity is r = sigmoid(-2z) (h = 1-2r folded into weights):
//   z*C = P'[tok] + C*S + sum_k r_k * (-2*C*Wh[k][lane])
//   e = 2^(z*C) = exp(2z);  r' = rcp(1+e)
// Serial tail per step: EX2 -> FADD -> RCP (~36cyc). Single syncwarp via
// double-buffered exchange. Packed f32x2 matvec (16 FFMA2). launch_bounds
// (128,1) lifts the 64-reg cap so all 8 exchange LDS.128 pipeline.
// ---------------------------------------------------------------------------
#define R_WARPS   4
#define R_THREADS 128

__global__ void __launch_bounds__(R_THREADS, 1)
rnn_kernel(const int*   __restrict__ tokens,
           const float* __restrict__ W1,
           const float* __restrict__ b1,
           const float* __restrict__ W2,
           const float* __restrict__ b2,
           const float* __restrict__ Wh,
           float*       __restrict__ out)
{
    __shared__ __align__(16) float h_s[R_WARPS][2][UNITS];
    __shared__ int tok_s[R_WARPS][MAXLEN];

    const unsigned FULL = 0xffffffffu;
    const int tid  = threadIdx.x;
    const int lane = tid & 31;
    const int wid  = tid >> 5;
    const int b    = blockIdx.x * R_WARPS + wid;

    // stage this block's 4 token rows
    {
        const int4* src = reinterpret_cast<const int4*>(tokens + blockIdx.x * R_WARPS * MAXLEN);
        int4* dst = reinterpret_cast<int4*>(&tok_s[0][0]);
        #pragma unroll
        for (int i = tid; i < R_WARPS * MAXLEN / 4; i += R_THREADS)
            dst[i] = src[i];
    }
    __syncthreads();

    // packed weights: whp[p] = {-2C*Wh[2p][lane], -2C*Wh[2p+1][lane]}
    // CS = C * sum_k Wh[k][lane]
    ull whp[UNITS / 2];
    float S = 0.f;
    #pragma unroll
    for (int p = 0; p < UNITS / 2; p++) {
        float wa = Wh[(2 * p)     * UNITS + lane];
        float wb = Wh[(2 * p + 1) * UNITS + lane];
        S += wa + wb;
        whp[p] = pack2(-2.f * CSCALE * wa, -2.f * CSCALE * wb);
    }
    const float CS = CSCALE * S;

    const int* trow = tok_s[wid];

    // depth-3 prefetch of scaled P rows (+CS pre-added)
    float pvS0 = g_P[trow[0] * UNITS + lane] + CS;
    float pvS1 = g_P[trow[1] * UNITS + lane] + CS;
    float pvS2 = g_P[trow[2] * UNITS + lane] + CS;

    float r = 0.5f;   // corresponds to h0 = 0

    #pragma unroll 4
    for (int t = 0; t < MAXLEN; t++) {
        float* buf = h_s[wid][t & 1];
        buf[lane] = r;
        __syncwarp();
        const ulonglong2* hb = reinterpret_cast<const ulonglong2*>(buf);
        ulonglong2 v0 = hb[0], v1 = hb[1], v2 = hb[2], v3 = hb[3];
        ulonglong2 v4 = hb[4], v5 = hb[5], v6 = hb[6], v7 = hb[7];

        // prefetch step t+3 (L2-resident, ~234cyc; 3 steps ≈ 360cyc)
        int t3 = (t + 3 < MAXLEN) ? (t + 3) : (MAXLEN - 1);
        float pvS3 = g_P[trow[t3] * UNITS + lane] + CS;

        ull A0 = pack2(pvS0, 0.f), A1 = 0ULL, A2 = 0ULL, A3 = 0ULL;
        A0 = fma2(v0.x, whp[0],  A0); A1 = fma2(v0.y, whp[1],  A1);
        A2 = fma2(v1.x, whp[2],  A2); A3 = fma2(v1.y, whp[3],  A3);
        A0 = fma2(v2.x, whp[4],  A0); A1 = fma2(v2.y, whp[5],  A1);
        A2 = fma2(v3.x, whp[6],  A2); A3 = fma2(v3.y, whp[7],  A3);
        A0 = fma2(v4.x, whp[8],  A0); A1 = fma2(v4.y, whp[9],  A1);
        A2 = fma2(v5.x, whp[10], A2); A3 = fma2(v5.y, whp[11], A3);
        A0 = fma2(v6.x, whp[12], A0); A1 = fma2(v6.y, whp[13], A1);
        A2 = fma2(v7.x, whp[14], A2); A3 = fma2(v7.y, whp[15], A3);

        ull Asum = add2(add2(A0, A1), add2(A2, A3));
        float zlo, zhi; unpack2(Asum, zlo, zhi);
        float zs = zlo + zhi;           // = C * z  (C = 2*log2 e)

        float e = ex2f(zs);             // = exp(2z)
        r = rcpf(1.f + e);              // = sigmoid(-2z); h = 1 - 2r = tanh(z)

        pvS0 = pvS1; pvS1 = pvS2; pvS2 = pvS3;
    }

    const float h = fmaf(-2.f, r, 1.f);

    // ---- head: z = (h @ W1 + b1) @ W2 + b2 ; out = sigmoid(z) ----
    float w1c[UNITS];
    #pragma unroll
    for (int k = 0; k < UNITS; k++)
        w1c[k] = (lane < F1) ? W1[k * F1 + lane] : 0.f;

    float y = (lane < F1) ? b1[lane] : 0.f;
    #pragma unroll
    for (int k = 0; k < UNITS; k++)
        y = fmaf(__shfl_sync(FULL, h, k), w1c[k], y);

    float w2v = (lane < F1) ? W2[lane] : 0.f;
    float contrib = y * w2v;
    #pragma unroll
    for (int off = 16; off > 0; off >>= 1)
        contrib += __shfl_xor_sync(FULL, contrib, off);

    if (lane == 0) {
        float zz = contrib + b2[0];
        out[b] = rcpf(1.f + ex2f(-1.4426950408889634f * zz));
    }
}

// ---------------------------------------------------------------------------
extern "C" void kernel_launch(void* const* d_in, const int* in_sizes, int n_in,
                              void* d_out, int out_size)
{
    const int*   tokens = (const int*)  d_in[0];
    const float* emb    = (const float*)d_in[1];
    const float* Wx     = (const float*)d_in[2];
    const float* Wh     = (const float*)d_in[3];
    const float* bias   = (const float*)d_in[4];
    const float* W1     = (const float*)d_in[5];
    const float* b1     = (const float*)d_in[6];
    const float* W2     = (const float*)d_in[7];
    const float* b2     = (const float*)d_in[8];
    float* out = (float*)d_out;

    cudaFuncSetAttribute((const void*)compute_P_kernel,
                         cudaFuncAttributeMaxDynamicSharedMemorySize, PK_SMEM);

    compute_P_kernel<<<(VOCAB + PK_ROWS - 1) / PK_ROWS, PK_THREADS, PK_SMEM>>>(emb, Wx, bias);
    rnn_kernel<<<BATCH / R_WARPS, R_THREADS>>>(tokens, W1, b1, W2, b2, Wh, out);
}

// round 4
// speedup vs baseline: 1.3935x; 1.1146x over previous
#include <cuda_runtime.h>

#define VOCAB  50000
#define EMBED  256
#define MAXLEN 512
#define UNITS  32
#define F1     16
#define BATCH  512

typedef unsigned long long ull;

// C = 2*log2(e): folds tanh's exp(2z)=2^(C*z) scaling into P and Wh.
#define CSCALE 2.8853900817779268f

// Scratch: P = C * (emb_table @ Wx + b)  [VOCAB, UNITS]  (6.4 MB, L2-resident)
__device__ float g_P[VOCAB * UNITS];

// ---- f32x2 packed helpers (sm_103a) --------------------------------------
__device__ __forceinline__ ull pack2(float lo, float hi) {
    ull d; asm("mov.b64 %0, {%1, %2};" : "=l"(d) : "f"(lo), "f"(hi)); return d;
}
__device__ __forceinline__ void unpack2(ull s, float& lo, float& hi) {
    asm("mov.b64 {%0, %1}, %2;" : "=f"(lo), "=f"(hi) : "l"(s));
}
__device__ __forceinline__ ull fma2(ull a, ull b, ull c) {
    ull d; asm("fma.rn.f32x2 %0, %1, %2, %3;" : "=l"(d) : "l"(a), "l"(b), "l"(c)); return d;
}
__device__ __forceinline__ ull add2(ull a, ull b) {
    ull d; asm("add.rn.f32x2 %0, %1, %2;" : "=l"(d) : "l"(a), "l"(b)); return d;
}
__device__ __forceinline__ float ex2f(float x) {
    float y; asm("ex2.approx.f32 %0, %1;" : "=f"(y) : "f"(x)); return y;
}
__device__ __forceinline__ float rcpf(float x) {
    float y; asm("rcp.approx.f32 %0, %1;" : "=f"(y) : "f"(x)); return y;
}

// ---------------------------------------------------------------------------
// Kernel 1: P[v][j] = C * (sum_e emb[v][e]*Wx[e][j] + b[j]), packed f32x2.
// (unchanged this round; ~20us, becomes co-bottleneck after rnn fix)
// ---------------------------------------------------------------------------
#define PK_ROWS    64
#define PK_THREADS 256
#define PK_SMEM    ((EMBED*UNITS + PK_ROWS*EMBED) * 4)   // 32KB + 64KB = 96KB

__global__ void __launch_bounds__(PK_THREADS, 1)
compute_P_kernel(const float* __restrict__ emb, const float* __restrict__ Wx,
                 const float* __restrict__ bias)
{
    extern __shared__ float smem[];
    float* wx_s  = smem;                  // [EMBED][UNITS]
    float* emb_s = smem + EMBED * UNITS;  // [PK_ROWS][EMBED]

    const int tid = threadIdx.x;
    const int v0  = blockIdx.x * PK_ROWS;

    #pragma unroll
    for (int i = tid; i < EMBED * UNITS; i += PK_THREADS)
        wx_s[i] = Wx[i];

    {
        const float4* e4  = reinterpret_cast<const float4*>(emb);
        float4*       es4 = reinterpret_cast<float4*>(emb_s);
        const int base4 = v0 * (EMBED / 4);
        const int max4  = VOCAB * (EMBED / 4);
        #pragma unroll
        for (int i = tid; i < PK_ROWS * (EMBED / 4); i += PK_THREADS) {
            int gi = base4 + i;
            es4[i] = (gi < max4) ? e4[gi] : make_float4(0.f, 0.f, 0.f, 0.f);
        }
    }
    __syncthreads();

    const int j  = tid & 31;
    const int rg = tid >> 5;
    const float* er = emb_s + rg * 8 * EMBED;
    const float bv = bias[j];

    ull acc[8];
    #pragma unroll
    for (int r = 0; r < 8; r++) acc[r] = pack2(bv, 0.f);

    #pragma unroll 4
    for (int e = 0; e < EMBED; e += 4) {
        const float w0 = wx_s[(e + 0) * UNITS + j];
        const float w1 = wx_s[(e + 1) * UNITS + j];
        const float w2 = wx_s[(e + 2) * UNITS + j];
        const float w3 = wx_s[(e + 3) * UNITS + j];
        const ull w01 = pack2(w0, w1);
        const ull w23 = pack2(w2, w3);
        #pragma unroll
        for (int r = 0; r < 8; r++) {
            ulonglong2 ev = *reinterpret_cast<const ulonglong2*>(er + r * EMBED + e);
            acc[r] = fma2(ev.x, w01, acc[r]);
            acc[r] = fma2(ev.y, w23, acc[r]);
        }
    }

    #pragma unroll
    for (int r = 0; r < 8; r++) {
        int v = v0 + rg * 8 + r;
        if (v < VOCAB) {
            float lo, hi; unpack2(acc[r], lo, hi);
            g_P[v * UNITS + j] = CSCALE * (lo + hi);
        }
    }
}

// ---------------------------------------------------------------------------
// Kernel 2: RNN recurrence + head. One warp per batch row, lane = unit.
//   z*C = P'[tok] + C*S + sum_k r_k * (-2*C*Wh[k][lane]);  r' = rcp(1 + 2^(zC))
// KEY FIX vs round 3: the P-row LDG is rotated RAW (no "+CS" at load site,
// which consumed the load in its own iteration and exposed 234cyc of L2
// latency every step). CS rides for free in the hi lane of the f32x2
// accumulator init: A0 = {pv, CS}. LDG for t+3 is issued at the top of the
// body, consumed 3 iterations (~400cyc) later.
// ---------------------------------------------------------------------------
#define R_WARPS   4
#define R_THREADS 128

__global__ void __launch_bounds__(R_THREADS, 1)
rnn_kernel(const int*   __restrict__ tokens,
           const float* __restrict__ W1,
           const float* __restrict__ b1,
           const float* __restrict__ W2,
           const float* __restrict__ b2,
           const float* __restrict__ Wh,
           float*       __restrict__ out)
{
    __shared__ __align__(16) float h_s[R_WARPS][2][UNITS];
    __shared__ int tok_s[R_WARPS][MAXLEN];

    const unsigned FULL = 0xffffffffu;
    const int tid  = threadIdx.x;
    const int lane = tid & 31;
    const int wid  = tid >> 5;
    const int b    = blockIdx.x * R_WARPS + wid;

    // stage this block's 4 token rows
    {
        const int4* src = reinterpret_cast<const int4*>(tokens + blockIdx.x * R_WARPS * MAXLEN);
        int4* dst = reinterpret_cast<int4*>(&tok_s[0][0]);
        #pragma unroll
        for (int i = tid; i < R_WARPS * MAXLEN / 4; i += R_THREADS)
            dst[i] = src[i];
    }
    __syncthreads();

    // packed weights: whp[p] = {-2C*Wh[2p][lane], -2C*Wh[2p+1][lane]}
    ull whp[UNITS / 2];
    float S = 0.f;
    #pragma unroll
    for (int p = 0; p < UNITS / 2; p++) {
        float wa = Wh[(2 * p)     * UNITS + lane];
        float wb = Wh[(2 * p + 1) * UNITS + lane];
        S += wa + wb;
        whp[p] = pack2(-2.f * CSCALE * wa, -2.f * CSCALE * wb);
    }
    const float CS = CSCALE * S;   // rides in accumulator hi lane

    const int* trow = tok_s[wid];

    // depth-3 prefetch ring of RAW P rows (no arithmetic attached!)
    float pv0 = g_P[trow[0] * UNITS + lane];
    float pv1 = g_P[trow[1] * UNITS + lane];
    float pv2 = g_P[trow[2] * UNITS + lane];

    float r = 0.5f;   // sigmoid(0): corresponds to h0 = 0

    #pragma unroll 8
    for (int t = 0; t < MAXLEN; t++) {
        // issue the t+3 LDG FIRST, raw into the ring (consumed 3 iters later)
        int t3 = (t + 3 < MAXLEN) ? (t + 3) : (MAXLEN - 1);
        float pv3 = g_P[trow[t3] * UNITS + lane];

        // exchange r across the warp (double-buffered, one sync)
        float* buf = h_s[wid][t & 1];
        buf[lane] = r;
        __syncwarp();
        const ulonglong2* hb = reinterpret_cast<const ulonglong2*>(buf);
        ulonglong2 v0 = hb[0], v1 = hb[1], v2 = hb[2], v3 = hb[3];
        ulonglong2 v4 = hb[4], v5 = hb[5], v6 = hb[6], v7 = hb[7];

        ull A0 = pack2(pv0, CS), A1 = 0ULL, A2 = 0ULL, A3 = 0ULL;
        A0 = fma2(v0.x, whp[0],  A0); A1 = fma2(v0.y, whp[1],  A1);
        A2 = fma2(v1.x, whp[2],  A2); A3 = fma2(v1.y, whp[3],  A3);
        A0 = fma2(v2.x, whp[4],  A0); A1 = fma2(v2.y, whp[5],  A1);
        A2 = fma2(v3.x, whp[6],  A2); A3 = fma2(v3.y, whp[7],  A3);
        A0 = fma2(v4.x, whp[8],  A0); A1 = fma2(v4.y, whp[9],  A1);
        A2 = fma2(v5.x, whp[10], A2); A3 = fma2(v5.y, whp[11], A3);
        A0 = fma2(v6.x, whp[12], A0); A1 = fma2(v6.y, whp[13], A1);
        A2 = fma2(v7.x, whp[14], A2); A3 = fma2(v7.y, whp[15], A3);

        ull Asum = add2(add2(A0, A1), add2(A2, A3));
        float zlo, zhi; unpack2(Asum, zlo, zhi);
        float zs = zlo + zhi;           // = C*z + ... (CS included via hi lane)

        float e = ex2f(zs);             // = exp(2z)
        r = rcpf(1.f + e);              // = sigmoid(-2z); h = 1 - 2r = tanh(z)

        pv0 = pv1; pv1 = pv2; pv2 = pv3;   // raw rotation -> pure renaming
    }

    const float h = fmaf(-2.f, r, 1.f);

    // ---- head: z = (h @ W1 + b1) @ W2 + b2 ; out = sigmoid(z) ----
    float w1c[UNITS];
    #pragma unroll
    for (int k = 0; k < UNITS; k++)
        w1c[k] = (lane < F1) ? W1[k * F1 + lane] : 0.f;

    float y = (lane < F1) ? b1[lane] : 0.f;
    #pragma unroll
    for (int k = 0; k < UNITS; k++)
        y = fmaf(__shfl_sync(FULL, h, k), w1c[k], y);

    float w2v = (lane < F1) ? W2[lane] : 0.f;
    float contrib = y * w2v;
    #pragma unroll
    for (int off = 16; off > 0; off >>= 1)
        contrib += __shfl_xor_sync(FULL, contrib, off);

    if (lane == 0) {
        float zz = contrib + b2[0];
        out[b] = rcpf(1.f + ex2f(-1.4426950408889634f * zz));
    }
}

// ---------------------------------------------------------------------------
extern "C" void kernel_launch(void* const* d_in, const int* in_sizes, int n_in,
                              void* d_out, int out_size)
{
    const int*   tokens = (const int*)  d_in[0];
    const float* emb    = (const float*)d_in[1];
    const float* Wx     = (const float*)d_in[2];
    const float* Wh     = (const float*)d_in[3];
    const float* bias   = (const float*)d_in[4];
    const float* W1     = (const float*)d_in[5];
    const float* b1     = (const float*)d_in[6];
    const float* W2     = (const float*)d_in[7];
    const float* b2     = (const float*)d_in[8];
    float* out = (float*)d_out;

    cudaFuncSetAttribute((const void*)compute_P_kernel,
                         cudaFuncAttributeMaxDynamicSharedMemorySize, PK_SMEM);

    compute_P_kernel<<<(VOCAB + PK_ROWS - 1) / PK_ROWS, PK_THREADS, PK_SMEM>>>(emb, Wx, bias);
    rnn_kernel<<<BATCH / R_WARPS, R_THREADS>>>(tokens, W1, b1, W2, b2, Wh, out);
}